// round 15
// baseline (speedup 1.0000x reference)
#include <cuda_runtime.h>
#include <cuda_bf16.h>

#define CDIM 8
#define NBLK 512                 // 8 slabs * 64 tiles (16x16 rows each)

__device__ double g_sum = 0.0;
__device__ double g_cnt = 0.0;
__device__ unsigned g_done = 0u;

// Interleaved 128-bit row ops: word c (x,y,z,w), bit i  <->  voxel 4i+c.
// Shift by +-1/+-2 voxels = word rotation (+ bit shift on the wrapped word).
__device__ __forceinline__ uint4 band(uint4 a, uint4 b) {
    return make_uint4(a.x & b.x, a.y & b.y, a.z & b.z, a.w & b.w);
}
__device__ __forceinline__ uint4 ishl1(uint4 a) {   // bit(v) <- bit(v-1)
    return make_uint4(a.w << 1, a.x, a.y, a.z);
}
__device__ __forceinline__ uint4 ishr1(uint4 a) {   // bit(v) <- bit(v+1)
    return make_uint4(a.y, a.z, a.w, a.x >> 1);
}
__device__ __forceinline__ uint4 ishl2(uint4 a) {
    return make_uint4(a.z << 1, a.w << 1, a.x, a.y);
}
__device__ __forceinline__ uint4 ishr2(uint4 a) {
    return make_uint4(a.z, a.w, a.x >> 1, a.y >> 1);
}

// Fused: ballot-pack targets (with halo) -> smem erosion -> BCE + reduction.
// Block = 16(d) x 16(h) rows x 128(w) voxels of one slab.
__global__ void __launch_bounds__(256, 4)
loss_kernel(const float* __restrict__ logits,
            const float* __restrict__ targets,
            const unsigned int* __restrict__ mask,
            const float* __restrict__ spatial,
            float* __restrict__ out)
{
    int blk = blockIdx.x;
    int slab = blk >> 6;                     // 64 tiles per slab
    int tile = blk & 63;
    int d0 = (tile >> 3) << 4;               // 8 x 8 tiles of 16 x 16
    int h0 = (tile & 7) << 4;
    int b = slab >> 2;
    int ch = ((slab & 3) << 1) + 1;

    __shared__ uint4 s_m[400];               // 20x20 halo rows of target bits
    __shared__ uint4 s_e[256];               // 16x16 eroded rows
    __shared__ float s_v[8], s_c[8];

    int t = threadIdx.x;
    int lane = t & 31, wid = t >> 5;
    float vsum = 0.0f, csum = 0.0f;

    if (mask[b * CDIM + ch] != 0u) {         // block-uniform
        size_t slabbase = ((size_t)(b * CDIM + ch)) << 21;

        // ---- Phase A: ballot-pack 400 halo rows (warp = one row per iter) ----
        for (int r = wid; r < 400; r += 8) {
            int dg = d0 - 2 + r / 20;
            int hg = h0 - 2 + r % 20;
            uint4 bits = make_uint4(0, 0, 0, 0);
            if ((unsigned)dg < 128u && (unsigned)hg < 128u) {
                const float4* src = (const float4*)(targets + slabbase +
                                     ((unsigned)dg << 14) + ((unsigned)hg << 7));
                float4 v = __ldg(src + lane);            // row fully coalesced
                bits.x = __ballot_sync(0xFFFFFFFFu, v.x > 0.5f);
                bits.y = __ballot_sync(0xFFFFFFFFu, v.y > 0.5f);
                bits.z = __ballot_sync(0xFFFFFFFFu, v.z > 0.5f);
                bits.w = __ballot_sync(0xFFFFFFFFu, v.w > 0.5f);
            }
            if (lane == 0) s_m[r] = bits;
        }
        __syncthreads();

        // ---- Phase B: erosion, one interior row per thread (smem only) ----
        {
            int dd = t >> 4, hh = t & 15;
            int dg = d0 + dd, hg = h0 + hh;
            int lc = (dd + 2) * 20 + hh + 2;             // local halo row index
            uint4 e = make_uint4(0, 0, 0, 0);
            if (dg >= 2 && dg <= 125 && hg >= 2 && hg <= 125) {
                uint4 M = s_m[lc];
                uint4 R = band(M, band(s_m[lc + 40], s_m[lc - 40]));   // d+-2
                R = band(R, band(s_m[lc + 2],  s_m[lc - 2]));          // h+-2
                R = band(R, band(s_m[lc + 21], s_m[lc + 19]));         // d+1,h+-1
                R = band(R, band(s_m[lc - 19], s_m[lc - 21]));         // d-1,h+-1
                uint4 q = band(band(s_m[lc + 20], s_m[lc - 20]),       // d+-1
                               band(s_m[lc + 1],  s_m[lc - 1]));       // h+-1
                uint4 u = band(M, q);
                e = band(band(R, u), band(ishl1(u), ishr1(u)));
                e = band(e, band(ishl2(M), ishr2(M)));
            }
            s_e[t] = e;
        }
        __syncthreads();

        // ---- Phase C: BCE (R12 layout: warp = 4 rows, lane: group l>>3, slot s) ----
        int s = lane & 7;
        int rg = lane >> 3;
        #pragma unroll
        for (int it = 0; it < 8; ++it) {
            int ri = wid * 32 + it * 4 + rg;             // interior row 0..255
            int dg = d0 + (ri >> 4), hg = h0 + (ri & 15);
            unsigned rowoff = ((unsigned)dg << 14) + ((unsigned)hg << 7) + (s << 2);
            const float* lp = logits + slabbase + rowoff;
            const float* pp = spatial + (((unsigned)b << 21) + rowoff);

            float4 lg0 = __ldg((const float4*)(lp));
            float4 lg1 = __ldg((const float4*)(lp + 32));
            float4 lg2 = __ldg((const float4*)(lp + 64));
            float4 lg3 = __ldg((const float4*)(lp + 96));
            float4 sm0 = __ldg((const float4*)(pp));
            float4 sm1 = __ldg((const float4*)(pp + 32));
            float4 sm2 = __ldg((const float4*)(pp + 64));
            float4 sm3 = __ldg((const float4*)(pp + 96));

            uint4 M = s_m[((ri >> 4) + 2) * 20 + (ri & 15) + 2];
            uint4 E = s_e[ri];
            unsigned nE0 = M.x & ~E.x, nE1 = M.y & ~E.y,
                     nE2 = M.z & ~E.z, nE3 = M.w & ~E.w;   // boundary words

            const float4 lgs[4] = {lg0, lg1, lg2, lg3};
            const float4 sms[4] = {sm0, sm1, sm2, sm3};
            #pragma unroll
            for (int j = 0; j < 4; ++j) {
                int I = s + 8 * j;                        // float4 chunk index
                unsigned tb0 = (M.x >> I) & 1u, bb0 = (nE0 >> I) & 1u;
                unsigned tb1 = (M.y >> I) & 1u, bb1 = (nE1 >> I) & 1u;
                unsigned tb2 = (M.z >> I) & 1u, bb2 = (nE2 >> I) & 1u;
                unsigned tb3 = (M.w >> I) & 1u, bb3 = (nE3 >> I) & 1u;
                const unsigned tbs[4] = {tb0, tb1, tb2, tb3};
                const unsigned bbs[4] = {bb0, bb1, bb2, bb3};
                #pragma unroll
                for (int k = 0; k < 4; ++k) {
                    float l  = (k == 0) ? lgs[j].x : (k == 1) ? lgs[j].y : (k == 2) ? lgs[j].z : lgs[j].w;
                    float sp = (k == 0) ? sms[j].x : (k == 1) ? sms[j].y : (k == 2) ? sms[j].z : sms[j].w;
                    // max(l,0) - l*t == max(sflip,0), sflip = t ? -l : l
                    float sflip = __uint_as_float(__float_as_uint(l) ^ (tbs[k] << 31));
                    float u = __expf(-fabsf(l));
                    float bce = fmaxf(sflip, 0.0f) + __logf(1.0f + u);
                    float wgt = bbs[k] ? 5.0f : 1.0f;
                    vsum += bce * wgt * sp;
                    csum += sp;
                }
            }
        }
    }

    // ---- Reduction + fused finalize (+ reset for next graph replay) ----
    #pragma unroll
    for (int off = 16; off > 0; off >>= 1) {
        vsum += __shfl_down_sync(0xFFFFFFFFu, vsum, off);
        csum += __shfl_down_sync(0xFFFFFFFFu, csum, off);
    }
    if (lane == 0) { s_v[wid] = vsum; s_c[wid] = csum; }
    __syncthreads();
    if (wid == 0) {
        vsum = (lane < 8) ? s_v[lane] : 0.0f;
        csum = (lane < 8) ? s_c[lane] : 0.0f;
        #pragma unroll
        for (int off = 4; off > 0; off >>= 1) {
            vsum += __shfl_down_sync(0xFFFFFFFFu, vsum, off);
            csum += __shfl_down_sync(0xFFFFFFFFu, csum, off);
        }
        if (lane == 0) {
            if (vsum != 0.0f) atomicAdd(&g_sum, (double)vsum);
            if (csum != 0.0f) atomicAdd(&g_cnt, (double)csum);
            __threadfence();
            unsigned ticket = atomicAdd(&g_done, 1u);
            if (ticket == NBLK - 1u) {               // last block finalizes
                double n = g_cnt;
                double ss = g_sum;
                out[0] = (n > 0.0) ? (float)(ss / (n > 1.0 ? n : 1.0)) : 0.0f;
                g_sum = 0.0;                         // reset for next replay
                g_cnt = 0.0;
                g_done = 0u;
            }
        }
    }
}

extern "C" void kernel_launch(void* const* d_in, const int* in_sizes, int n_in,
                              void* d_out, int out_size) {
    const float*        logits  = (const float*)d_in[0];
    const float*        targets = (const float*)d_in[1];
    const unsigned int* mask    = (const unsigned int*)d_in[2];
    const float*        spatial = (const float*)d_in[3];
    float*              out     = (float*)d_out;

    loss_kernel<<<NBLK, 256>>>(logits, targets, mask, spatial, out);
}